// round 2
// baseline (speedup 1.0000x reference)
#include <cuda_runtime.h>
#include <cuda_bf16.h>
#include <math.h>

// ---------------------------------------------------------------------------
// UCBAttention fused implementation (fp32)
//   out       [B,N,C]   = proj( prunedAttn(x) )
//   score_delta [H,N,N] = sum over batch of top-k masks
// Fixed shapes: N=1024, C=768, H=12, Dh=64, TOPK=128, BETA=1
// ---------------------------------------------------------------------------

#define N_TOK   1024
#define CDIM    768
#define HNUM    12
#define DH      64
#define TOPK    128
#define RPB     8          // query rows per attention block
#define NTHR    256
#define MAXB    4

// Scratch (device globals -- no allocation allowed)
__device__ float g_qkv[3ull * MAXB * HNUM * N_TOK * DH];  // [3,B,H,N,Dh]
__device__ float g_ctx[(size_t)MAXB * N_TOK * CDIM];      // [B,N,H,Dh] = [B,N,C]

// ---------------------------------------------------------------------------
// Tiled fp32 GEMM: C[m,n] = sum_k A[m,k] * W[n,k]   (torch Linear style)
// 64x64 tile, BK=16, 256 threads, 4x4 microtile.
// ---------------------------------------------------------------------------
#define BK   16
#define BMN  64

// QKV: A = x [B*N, 768], W = qkv_w [2304, 768], scatter into g_qkv[3,B,H,N,Dh]
__global__ __launch_bounds__(256) void qkv_gemm_kernel(
    const float* __restrict__ x, const float* __restrict__ w, int B)
{
    __shared__ float As[BK][BMN + 4];
    __shared__ float Bs[BK][BMN + 4];
    const int row0 = blockIdx.y * BMN;
    const int col0 = blockIdx.x * BMN;
    const int tid  = threadIdx.x;
    const int tx   = tid & 15, ty = tid >> 4;
    const int K    = CDIM;

    float acc[4][4];
#pragma unroll
    for (int i = 0; i < 4; i++)
#pragma unroll
        for (int j = 0; j < 4; j++) acc[i][j] = 0.f;

    for (int k0 = 0; k0 < K; k0 += BK) {
#pragma unroll
        for (int p = 0; p < 4; p++) {
            int r = (tid >> 4) + p * 16;
            int c = tid & 15;
            As[c][r] = x[(size_t)(row0 + r) * K + k0 + c];
            Bs[c][r] = w[(size_t)(col0 + r) * K + k0 + c];
        }
        __syncthreads();
#pragma unroll
        for (int kk = 0; kk < BK; kk++) {
            float4 av = *(const float4*)&As[kk][ty * 4];
            float4 bv = *(const float4*)&Bs[kk][tx * 4];
            float a[4] = {av.x, av.y, av.z, av.w};
            float b[4] = {bv.x, bv.y, bv.z, bv.w};
#pragma unroll
            for (int i = 0; i < 4; i++)
#pragma unroll
                for (int j = 0; j < 4; j++) acc[i][j] += a[i] * b[j];
        }
        __syncthreads();
    }

    // Scatter: col index c3 in [0,2304) -> (which = c3/768, h = (c3%768)/64, d = c3%64)
    // col0 is 64-aligned, tile spans exactly one (which, h). row0 is 64-aligned -> one b.
    const int which = col0 / CDIM;
    const int h     = (col0 % CDIM) / DH;
    const int b     = row0 / N_TOK;
    const int n0    = row0 % N_TOK;
    size_t base = (((size_t)which * B + b) * HNUM + h) * (size_t)N_TOK * DH;
#pragma unroll
    for (int i = 0; i < 4; i++) {
        int n = n0 + ty * 4 + i;
#pragma unroll
        for (int j = 0; j < 4; j++) {
            int d = tx * 4 + j;
            g_qkv[base + (size_t)n * DH + d] = acc[i][j];
        }
    }
}

// Proj: A = g_ctx [B*N, 768], W = proj_w [768,768], + bias, plain write to out
__global__ __launch_bounds__(256) void proj_gemm_kernel(
    const float* __restrict__ w, const float* __restrict__ bias,
    float* __restrict__ out)
{
    __shared__ float As[BK][BMN + 4];
    __shared__ float Bs[BK][BMN + 4];
    const int row0 = blockIdx.y * BMN;
    const int col0 = blockIdx.x * BMN;
    const int tid  = threadIdx.x;
    const int tx   = tid & 15, ty = tid >> 4;
    const int K    = CDIM;

    float acc[4][4];
#pragma unroll
    for (int i = 0; i < 4; i++)
#pragma unroll
        for (int j = 0; j < 4; j++) acc[i][j] = 0.f;

    for (int k0 = 0; k0 < K; k0 += BK) {
#pragma unroll
        for (int p = 0; p < 4; p++) {
            int r = (tid >> 4) + p * 16;
            int c = tid & 15;
            As[c][r] = g_ctx[(size_t)(row0 + r) * K + k0 + c];
            Bs[c][r] = w[(size_t)(col0 + r) * K + k0 + c];
        }
        __syncthreads();
#pragma unroll
        for (int kk = 0; kk < BK; kk++) {
            float4 av = *(const float4*)&As[kk][ty * 4];
            float4 bv = *(const float4*)&Bs[kk][tx * 4];
            float a[4] = {av.x, av.y, av.z, av.w};
            float b[4] = {bv.x, bv.y, bv.z, bv.w};
#pragma unroll
            for (int i = 0; i < 4; i++)
#pragma unroll
                for (int j = 0; j < 4; j++) acc[i][j] += a[i] * b[j];
        }
        __syncthreads();
    }
#pragma unroll
    for (int i = 0; i < 4; i++) {
        int r = row0 + ty * 4 + i;
#pragma unroll
        for (int j = 0; j < 4; j++) {
            int c = col0 + tx * 4 + j;
            out[(size_t)r * CDIM + c] = acc[i][j] + bias[c];
        }
    }
}

// ---------------------------------------------------------------------------
// Fused attention: scores -> softmax stats -> UCB top-128 (radix select)
//                  -> pruned renormalized context -> score_delta atomics
// One block handles RPB=8 query rows of one (b,h).
// ---------------------------------------------------------------------------
__global__ __launch_bounds__(256) void attn_topk_kernel(
    int B, const float* __restrict__ count,
    const int* __restrict__ counter_p, const int* __restrict__ enabled_p,
    float* __restrict__ sd)
{
    __shared__ float qs[RPB][DH];
    __shared__ float s[RPB][N_TOK];          // 32 KB scores
    __shared__ unsigned int u[N_TOK];        // ordered ucb keys
    __shared__ float red[NTHR];
    __shared__ unsigned int hist[16];
    __shared__ int sel_idx[TOPK];
    __shared__ float sel_w[TOPK];
    __shared__ float cpart[4][DH];
    __shared__ int tieb[256];
    __shared__ int nsel_sh, ntie_sh, kneed_sh;
    __shared__ unsigned int prefix_sh;

    const int tid = threadIdx.x;
    const int nbi = N_TOK / RPB;
    const int bh  = blockIdx.x / nbi;
    const int i0  = (blockIdx.x % nbi) * RPB;
    const int b   = bh / HNUM;
    const int h   = bh % HNUM;

    const size_t plane = (size_t)B * HNUM * N_TOK * DH;
    const float* qp = g_qkv + (size_t)bh * N_TOK * DH;
    const float* kp = g_qkv + plane + (size_t)bh * N_TOK * DH;
    const float* vp = g_qkv + 2 * plane + (size_t)bh * N_TOK * DH;

    // Robust scalar read: handle int32 or float32 encodings of counter/enabled.
    int cnt = counter_p[0];
    if (cnt < 0 || cnt > 1000000) cnt = (int)__int_as_float(cnt);
    int en = enabled_p[0];
    if (en < 0 || en > 1000000) en = (int)__int_as_float(en);
    const bool ucb = (sd != nullptr) && (en != 0) && (cnt > 50);
    const float logc = logf((float)cnt + 1.0f);

    for (int t = tid; t < RPB * DH; t += NTHR)
        qs[t >> 6][t & 63] = qp[(size_t)(i0 + (t >> 6)) * DH + (t & 63)];
    __syncthreads();

    const float scale = 0.125f;  // 64^-0.5

    // ---- scores for 8 rows: each thread owns 4 key columns j ----
    for (int j = tid; j < N_TOK; j += NTHR) {
        const float4* kr = (const float4*)(kp + (size_t)j * DH);
        float acc[RPB];
#pragma unroll
        for (int r = 0; r < RPB; r++) acc[r] = 0.f;
#pragma unroll
        for (int d4 = 0; d4 < DH / 4; d4++) {
            float4 kv = kr[d4];
#pragma unroll
            for (int r = 0; r < RPB; r++) {
                float4 qv = *(const float4*)&qs[r][d4 * 4];
                acc[r] += kv.x * qv.x + kv.y * qv.y + kv.z * qv.z + kv.w * qv.w;
            }
        }
#pragma unroll
        for (int r = 0; r < RPB; r++) s[r][j] = acc[r] * scale;
    }
    __syncthreads();

    for (int r = 0; r < RPB; r++) {
        const int i = i0 + r;

        // row max
        float m = -3.0e38f;
        for (int j = tid; j < N_TOK; j += NTHR) m = fmaxf(m, s[r][j]);
        red[tid] = m; __syncthreads();
        for (int st = NTHR / 2; st > 0; st >>= 1) {
            if (tid < st) red[tid] = fmaxf(red[tid], red[tid + st]);
            __syncthreads();
        }
        m = red[0]; __syncthreads();

        // softmax denominator Z
        float z = 0.f;
        for (int j = tid; j < N_TOK; j += NTHR) z += expf(s[r][j] - m);
        red[tid] = z; __syncthreads();
        for (int st = NTHR / 2; st > 0; st >>= 1) {
            if (tid < st) red[tid] += red[tid + st];
            __syncthreads();
        }
        const float Z = red[0]; __syncthreads();

        if (ucb) {
            // ucb keys -> order-preserving uint32
            const float* crow = count + ((size_t)h * N_TOK + i) * N_TOK;
            for (int j = tid; j < N_TOK; j += NTHR) {
                float uv = s[r][j] + sqrtf(logc / (crow[j] + 1e-6f));  // BETA=1
                unsigned ub = __float_as_uint(uv);
                ub = (ub & 0x80000000u) ? ~ub : (ub | 0x80000000u);
                u[j] = ub;
            }
            if (tid == 0) { prefix_sh = 0u; kneed_sh = TOPK; }
            __syncthreads();

            // 8x4-bit radix select for the 128th-largest key
            for (int shift = 28; shift >= 0; shift -= 4) {
                if (tid < 16) hist[tid] = 0u;
                __syncthreads();
                const unsigned mhi = (shift == 28) ? 0u : (0xFFFFFFFFu << (shift + 4));
                const unsigned pref = prefix_sh;
                for (int j = tid; j < N_TOK; j += NTHR) {
                    unsigned uv = u[j];
                    if ((uv & mhi) == pref) atomicAdd(&hist[(uv >> shift) & 15], 1u);
                }
                __syncthreads();
                if (tid == 0) {
                    unsigned kacc = 0; int need = kneed_sh; int bsel = 0;
                    for (int bin = 15; bin >= 0; --bin) {
                        unsigned c = hist[bin];
                        if (kacc + c >= (unsigned)need) { bsel = bin; break; }
                        kacc += c;
                    }
                    prefix_sh |= ((unsigned)bsel) << shift;
                    kneed_sh = need - (int)kacc;
                }
                __syncthreads();
            }
            const unsigned T = prefix_sh;
            const int ktie = kneed_sh;   // how many ties at T to take (smallest idx first)
            if (tid == 0) { nsel_sh = 0; ntie_sh = 0; }
            __syncthreads();

            for (int j = tid; j < N_TOK; j += NTHR) {
                unsigned uv = u[j];
                if (uv > T) {
                    int p = atomicAdd(&nsel_sh, 1);
                    if (p < TOPK) sel_idx[p] = j;
                } else if (uv == T) {
                    int p = atomicAdd(&ntie_sh, 1);
                    if (p < 256) tieb[p] = j;
                }
            }
            __syncthreads();
            if (tid == 0) {
                int nt = ntie_sh; if (nt > 256) nt = 256;
                for (int a = 1; a < nt; a++) {     // tiny insertion sort (nt is ~1)
                    int v = tieb[a]; int p = a - 1;
                    while (p >= 0 && tieb[p] > v) { tieb[p + 1] = tieb[p]; p--; }
                    tieb[p + 1] = v;
                }
            }
            __syncthreads();
            if (tid < ktie) sel_idx[nsel_sh + tid] = tieb[tid];
            __syncthreads();

            // weights e_j = exp(s-m); pruned_j = e_j / (psum_e + 1e-8 * Z)
            if (tid < TOPK) sel_w[tid] = expf(s[r][sel_idx[tid]] - m);
            __syncthreads();
            red[tid] = (tid < TOPK) ? sel_w[tid] : 0.f;
            __syncthreads();
            for (int st = NTHR / 2; st > 0; st >>= 1) {
                if (tid < st) red[tid] += red[tid + st];
                __syncthreads();
            }
            const float denom = red[0] + 1e-8f * Z;
            __syncthreads();

            // context: 4 groups x 64 dims
            const int g = tid >> 6, d = tid & 63;
            float acc = 0.f;
            for (int t = g; t < TOPK; t += 4)
                acc += sel_w[t] * vp[(size_t)sel_idx[t] * DH + d];
            cpart[g][d] = acc; __syncthreads();
            if (g == 0) {
                float tot = (cpart[0][d] + cpart[1][d] + cpart[2][d] + cpart[3][d]) / denom;
                g_ctx[((size_t)(b * N_TOK + i) * HNUM + h) * DH + d] = tot;
            }
            if (tid < TOPK)
                atomicAdd(&sd[((size_t)h * N_TOK + i) * N_TOK + sel_idx[tid]], 1.0f);
            __syncthreads();
        } else {
            // dense path (not taken with provided inputs, kept for correctness)
            const int g = tid >> 6, d = tid & 63;
            float acc = 0.f;
            for (int j = g; j < N_TOK; j += 4)
                acc += expf(s[r][j] - m) * vp[(size_t)j * DH + d];
            cpart[g][d] = acc; __syncthreads();
            if (g == 0)
                g_ctx[((size_t)(b * N_TOK + i) * HNUM + h) * DH + d] =
                    (cpart[0][d] + cpart[1][d] + cpart[2][d] + cpart[3][d]) / Z;
            __syncthreads();
        }
    }
}

// ---------------------------------------------------------------------------
extern "C" void kernel_launch(void* const* d_in, const int* in_sizes, int n_in,
                              void* d_out, int out_size)
{
    const float* x      = (const float*)d_in[0];
    const float* qkv_w  = (const float*)d_in[1];
    const float* proj_w = (const float*)d_in[2];
    const float* proj_b = (const float*)d_in[3];
    const float* cscore = (const float*)d_in[4];
    const int*   cntr   = (const int*)d_in[5];
    const int*   enab   = (const int*)d_in[6];

    int B = in_sizes[0] / (N_TOK * CDIM);
    if (B < 1) B = 1;
    if (B > MAXB) B = MAXB;

    float* out = (float*)d_out;
    const size_t out_elems = (size_t)B * N_TOK * CDIM;
    const size_t sd_elems  = (size_t)HNUM * N_TOK * N_TOK;
    float* sd = nullptr;
    if ((size_t)out_size >= out_elems + sd_elems) {
        sd = out + out_elems;
        cudaMemsetAsync(sd, 0, sd_elems * sizeof(float));
    }

    dim3 qg(3 * CDIM / BMN, (B * N_TOK) / BMN);   // 36 x 64
    qkv_gemm_kernel<<<qg, 256>>>(x, qkv_w, B);

    attn_topk_kernel<<<B * HNUM * (N_TOK / RPB), 256>>>(B, cscore, cntr, enab, sd);

    dim3 pg(CDIM / BMN, (B * N_TOK) / BMN);       // 12 x 64
    proj_gemm_kernel<<<pg, 256>>>(proj_w, proj_b, out);
}

// round 3
// speedup vs baseline: 1.2278x; 1.2278x over previous
#include <cuda_runtime.h>
#include <cuda_bf16.h>
#include <math.h>

// ---------------------------------------------------------------------------
// UCBAttention fused implementation (fp32)
//   out         [B,N,C]  = proj( prunedAttn(x) )
//   score_delta [H,N,N]  = sum over batch of top-k masks
// Fixed shapes: N=1024, C=768, H=12, Dh=64, TOPK=128, BETA=1
// ---------------------------------------------------------------------------

#define N_TOK   1024
#define CDIM    768
#define HNUM    12
#define DH      64
#define TOPK    128
#define RPB     8          // query rows per attention block (= warps per block)
#define NTHR    256
#define MAXB    4
#define FULLM   0xFFFFFFFFu

// Scratch (device globals -- no allocation allowed)
__device__ float g_qkv[3ull * MAXB * HNUM * N_TOK * DH];  // [3,B,H,N,Dh]
__device__ float g_ctx[(size_t)MAXB * N_TOK * CDIM];      // [B,N,H,Dh] = [B,N,C]

// ---------------------------------------------------------------------------
// Tiled fp32 GEMM: C[m,n] = sum_k A[m,k] * W[n,k]   (torch Linear style)
// 64x64 tile, BK=16, 256 threads, 4x4 microtile.
// ---------------------------------------------------------------------------
#define BK   16
#define BMN  64

__global__ __launch_bounds__(256) void qkv_gemm_kernel(
    const float* __restrict__ x, const float* __restrict__ w, int B)
{
    __shared__ float As[BK][BMN + 4];
    __shared__ float Bs[BK][BMN + 4];
    const int row0 = blockIdx.y * BMN;
    const int col0 = blockIdx.x * BMN;
    const int tid  = threadIdx.x;
    const int tx   = tid & 15, ty = tid >> 4;
    const int K    = CDIM;

    float acc[4][4];
#pragma unroll
    for (int i = 0; i < 4; i++)
#pragma unroll
        for (int j = 0; j < 4; j++) acc[i][j] = 0.f;

    for (int k0 = 0; k0 < K; k0 += BK) {
#pragma unroll
        for (int p = 0; p < 4; p++) {
            int r = (tid >> 4) + p * 16;
            int c = tid & 15;
            As[c][r] = x[(size_t)(row0 + r) * K + k0 + c];
            Bs[c][r] = w[(size_t)(col0 + r) * K + k0 + c];
        }
        __syncthreads();
#pragma unroll
        for (int kk = 0; kk < BK; kk++) {
            float4 av = *(const float4*)&As[kk][ty * 4];
            float4 bv = *(const float4*)&Bs[kk][tx * 4];
            float a[4] = {av.x, av.y, av.z, av.w};
            float b[4] = {bv.x, bv.y, bv.z, bv.w};
#pragma unroll
            for (int i = 0; i < 4; i++)
#pragma unroll
                for (int j = 0; j < 4; j++) acc[i][j] += a[i] * b[j];
        }
        __syncthreads();
    }

    const int which = col0 / CDIM;
    const int h     = (col0 % CDIM) / DH;
    const int b     = row0 / N_TOK;
    const int n0    = row0 % N_TOK;
    size_t base = (((size_t)which * B + b) * HNUM + h) * (size_t)N_TOK * DH;
#pragma unroll
    for (int i = 0; i < 4; i++) {
        int n = n0 + ty * 4 + i;
#pragma unroll
        for (int j = 0; j < 4; j++) {
            int d = tx * 4 + j;
            g_qkv[base + (size_t)n * DH + d] = acc[i][j];
        }
    }
}

__global__ __launch_bounds__(256) void proj_gemm_kernel(
    const float* __restrict__ w, const float* __restrict__ bias,
    float* __restrict__ out)
{
    __shared__ float As[BK][BMN + 4];
    __shared__ float Bs[BK][BMN + 4];
    const int row0 = blockIdx.y * BMN;
    const int col0 = blockIdx.x * BMN;
    const int tid  = threadIdx.x;
    const int tx   = tid & 15, ty = tid >> 4;
    const int K    = CDIM;

    float acc[4][4];
#pragma unroll
    for (int i = 0; i < 4; i++)
#pragma unroll
        for (int j = 0; j < 4; j++) acc[i][j] = 0.f;

    for (int k0 = 0; k0 < K; k0 += BK) {
#pragma unroll
        for (int p = 0; p < 4; p++) {
            int r = (tid >> 4) + p * 16;
            int c = tid & 15;
            As[c][r] = g_ctx[(size_t)(row0 + r) * K + k0 + c];
            Bs[c][r] = w[(size_t)(col0 + r) * K + k0 + c];
        }
        __syncthreads();
#pragma unroll
        for (int kk = 0; kk < BK; kk++) {
            float4 av = *(const float4*)&As[kk][ty * 4];
            float4 bv = *(const float4*)&Bs[kk][tx * 4];
            float a[4] = {av.x, av.y, av.z, av.w};
            float b[4] = {bv.x, bv.y, bv.z, bv.w};
#pragma unroll
            for (int i = 0; i < 4; i++)
#pragma unroll
                for (int j = 0; j < 4; j++) acc[i][j] += a[i] * b[j];
        }
        __syncthreads();
    }
#pragma unroll
    for (int i = 0; i < 4; i++) {
        int r = row0 + ty * 4 + i;
#pragma unroll
        for (int j = 0; j < 4; j++) {
            int c = col0 + tx * 4 + j;
            out[(size_t)r * CDIM + c] = acc[i][j] + bias[c];
        }
    }
}

// ---------------------------------------------------------------------------
// Fused attention, warp-per-row.
// Block: 256 threads = 8 warps; cooperatively computes scores for 8 rows of
// one (b,h), then warp w handles row w end-to-end (no block barriers).
// Dynamic smem: qs[8][64] floats, su[8][1024] uint (scores, then ucb keys).
// ---------------------------------------------------------------------------
__global__ __launch_bounds__(256) void attn_topk_kernel(
    int B, const float* __restrict__ count,
    const int* __restrict__ counter_p, const int* __restrict__ enabled_p,
    float* __restrict__ sd)
{
    extern __shared__ unsigned int dynsh[];
    float*        qs = (float*)dynsh;              // [8][64]
    unsigned int* su = dynsh + RPB * DH;           // [8][1024] score bits / keys

    __shared__ unsigned int hist[RPB][256];        // per-warp radix histogram
    __shared__ int   sel_idx[RPB][TOPK];
    __shared__ float sel_w [RPB][TOPK];

    const int tid  = threadIdx.x;
    const int lane = tid & 31;
    const int wrp  = tid >> 5;
    const unsigned lmask_lt = (1u << lane) - 1u;

    const int nbi = N_TOK / RPB;
    const int bh  = blockIdx.x / nbi;
    const int i0  = (blockIdx.x % nbi) * RPB;
    const int b   = bh / HNUM;
    const int h   = bh % HNUM;

    const size_t plane = (size_t)B * HNUM * N_TOK * DH;
    const float* qp = g_qkv + (size_t)bh * N_TOK * DH;
    const float* kp = g_qkv + plane + (size_t)bh * N_TOK * DH;
    const float* vp = g_qkv + 2 * plane + (size_t)bh * N_TOK * DH;

    // Robust scalar read: handle int32 or float32 encodings of counter/enabled.
    int cnt = counter_p[0];
    if (cnt < 0 || cnt > 1000000) cnt = (int)__int_as_float(cnt);
    int en = enabled_p[0];
    if (en < 0 || en > 1000000) en = (int)__int_as_float(en);
    const bool ucb = (sd != nullptr) && (en != 0) && (cnt > 50);
    const float logc = logf((float)cnt + 1.0f);

    for (int t = tid; t < RPB * DH; t += NTHR)
        qs[t] = qp[(size_t)(i0 + (t >> 6)) * DH + (t & 63)];
    __syncthreads();

    const float scale = 0.125f;  // 64^-0.5

    // ---- scores for 8 rows: each thread owns 4 key columns j ----
    for (int j = tid; j < N_TOK; j += NTHR) {
        const float4* kr = (const float4*)(kp + (size_t)j * DH);
        float acc[RPB];
#pragma unroll
        for (int r = 0; r < RPB; r++) acc[r] = 0.f;
#pragma unroll
        for (int d4 = 0; d4 < DH / 4; d4++) {
            float4 kv = kr[d4];
#pragma unroll
            for (int r = 0; r < RPB; r++) {
                float4 qv = *(const float4*)&qs[r * DH + d4 * 4];
                acc[r] += kv.x * qv.x + kv.y * qv.y + kv.z * qv.z + kv.w * qv.w;
            }
        }
#pragma unroll
        for (int r = 0; r < RPB; r++)
            su[r * N_TOK + j] = __float_as_uint(acc[r] * scale);
    }
    __syncthreads();

    // =================== warp-per-row phase (no block barriers) =============
    const int r = wrp;
    const int i = i0 + r;
    unsigned int* urow = su + r * N_TOK;
    const float* crow  = count + ((size_t)h * N_TOK + i) * N_TOK;

    // ---- online (m, Z) ----
    float m = -3.0e38f, z = 0.f;
#pragma unroll 4
    for (int jj = 0; jj < 32; jj++) {
        float v = __uint_as_float(urow[lane + (jj << 5)]);
        if (v > m) { z = z * expf(m - v) + 1.0f; m = v; }
        else       { z += expf(v - m); }
    }
#pragma unroll
    for (int off = 16; off > 0; off >>= 1) {
        float om = __shfl_xor_sync(FULLM, m, off);
        float oz = __shfl_xor_sync(FULLM, z, off);
        float nm = fmaxf(m, om);
        z = z * expf(m - nm) + oz * expf(om - nm);
        m = nm;
    }
    const float Z = z;

    if (ucb) {
        // ---- overwrite scores with order-preserving uint32 ucb keys ----
#pragma unroll 4
        for (int jj = 0; jj < 32; jj++) {
            int j = lane + (jj << 5);
            float sv = __uint_as_float(urow[j]);
            float uv = sv + sqrtf(logc / (crow[j] + 1e-6f));   // BETA=1
            unsigned ub = __float_as_uint(uv);
            ub = (ub & 0x80000000u) ? ~ub : (ub | 0x80000000u);
            urow[j] = ub;
        }
        __syncwarp();

        // ---- 4 x 8-bit radix select for 128th-largest key ----
        unsigned pref = 0u;
        int need = TOPK;
#pragma unroll
        for (int shift = 24; shift >= 0; shift -= 8) {
            for (int bb = lane; bb < 256; bb += 32) hist[r][bb] = 0u;
            __syncwarp();
            const unsigned mhi = (shift == 24) ? 0u : (0xFFFFFFFFu << (shift + 8));
#pragma unroll 4
            for (int jj = 0; jj < 32; jj++) {
                unsigned uv = urow[lane + (jj << 5)];
                if ((uv & mhi) == pref)
                    atomicAdd(&hist[r][(uv >> shift) & 255], 1u);
            }
            __syncwarp();
            // lane l owns bin group [248-8l .. 255-8l] (lane 0 = topmost)
            const int gbase = 248 - (lane << 3);
            unsigned gsum = 0;
#pragma unroll
            for (int t = 0; t < 8; t++) gsum += hist[r][gbase + t];
            // inclusive prefix over lanes (descending bin order)
            unsigned pre = gsum;
#pragma unroll
            for (int off = 1; off < 32; off <<= 1) {
                unsigned o = __shfl_up_sync(FULLM, pre, off);
                if (lane >= off) pre += o;
            }
            const unsigned above = pre - gsum;
            bool hit = (above < (unsigned)need) && ((unsigned)need <= pre);
            unsigned hm = __ballot_sync(FULLM, hit);
            int hl = __ffs(hm) - 1;
            int bsel = 0; unsigned kacc = 0;
            if (lane == hl) {
                unsigned acc2 = above;
                for (int bb = gbase + 7; bb >= gbase; --bb) {
                    unsigned c = hist[r][bb];
                    if (acc2 + c >= (unsigned)need) { bsel = bb; kacc = acc2; break; }
                    acc2 += c;
                }
            }
            bsel = __shfl_sync(FULLM, bsel, hl);
            kacc = __shfl_sync(FULLM, kacc, hl);
            pref |= ((unsigned)bsel) << shift;
            need -= (int)kacc;
        }
        const unsigned T = pref;

        // ---- compaction: all keys > T (ascending j), then ties ascending j ----
        int base = 0;
        for (int jj = 0; jj < 32; jj++) {
            int j = lane + (jj << 5);
            unsigned uv = urow[j];
            bool g = uv > T;
            unsigned bal = __ballot_sync(FULLM, g);
            if (g) sel_idx[r][base + __popc(bal & lmask_lt)] = j;
            base += __popc(bal);
        }
        for (int jj = 0; jj < 32 && base < TOPK; jj++) {
            int j = lane + (jj << 5);
            unsigned uv = urow[j];
            bool t = (uv == T);
            unsigned bal = __ballot_sync(FULLM, t);
            if (t) {
                int pos = base + __popc(bal & lmask_lt);
                if (pos < TOPK) sel_idx[r][pos] = j;
            }
            base += __popc(bal);
        }
        __syncwarp();

        // ---- weights: s_sel = invOrd(key) - expl, e = exp(s_sel - m) ----
        float psum = 0.f;
        float ev[4];
#pragma unroll
        for (int q = 0; q < 4; q++) {
            int p = lane + (q << 5);
            int idx = sel_idx[r][p];
            unsigned uv = urow[idx];
            unsigned fb = (uv & 0x80000000u) ? (uv & 0x7FFFFFFFu) : ~uv;
            float ucbv = __uint_as_float(fb);
            float sv = ucbv - sqrtf(logc / (crow[idx] + 1e-6f));
            ev[q] = expf(sv - m);
            psum += ev[q];
        }
#pragma unroll
        for (int off = 16; off > 0; off >>= 1)
            psum += __shfl_xor_sync(FULLM, psum, off);
        const float denom = psum + 1e-8f * Z;
#pragma unroll
        for (int q = 0; q < 4; q++) sel_w[r][lane + (q << 5)] = ev[q];
        __syncwarp();

        // ---- context: lane owns dims (lane, lane+32) ----
        float a0 = 0.f, a1 = 0.f;
#pragma unroll 4
        for (int p = 0; p < TOPK; p++) {
            int idx = sel_idx[r][p];        // LDS broadcast
            float wv = sel_w[r][p];
            const float* vr = vp + (size_t)idx * DH;
            a0 += wv * vr[lane];
            a1 += wv * vr[lane + 32];
        }
        float* cdst = g_ctx + ((size_t)(b * N_TOK + i) * HNUM + h) * DH;
        cdst[lane]      = a0 / denom;
        cdst[lane + 32] = a1 / denom;

        // ---- score_delta ----
        float* srow = sd + ((size_t)h * N_TOK + i) * N_TOK;
#pragma unroll
        for (int q = 0; q < 4; q++)
            atomicAdd(&srow[sel_idx[r][lane + (q << 5)]], 1.0f);
    } else {
        // dense fallback (not taken with the provided inputs)
#pragma unroll 4
        for (int jj = 0; jj < 32; jj++) {
            int j = lane + (jj << 5);
            float e = expf(__uint_as_float(urow[j]) - m);
            urow[j] = __float_as_uint(e);
        }
        __syncwarp();
        float a0 = 0.f, a1 = 0.f;
        for (int p = 0; p < N_TOK; p++) {
            float wv = __uint_as_float(urow[p]);
            const float* vr = vp + (size_t)p * DH;
            a0 += wv * vr[lane];
            a1 += wv * vr[lane + 32];
        }
        float* cdst = g_ctx + ((size_t)(b * N_TOK + i) * HNUM + h) * DH;
        cdst[lane]      = a0 / Z;
        cdst[lane + 32] = a1 / Z;
    }
}

// ---------------------------------------------------------------------------
extern "C" void kernel_launch(void* const* d_in, const int* in_sizes, int n_in,
                              void* d_out, int out_size)
{
    const float* x      = (const float*)d_in[0];
    const float* qkv_w  = (const float*)d_in[1];
    const float* proj_w = (const float*)d_in[2];
    const float* proj_b = (const float*)d_in[3];
    const float* cscore = (const float*)d_in[4];
    const int*   cntr   = (const int*)d_in[5];
    const int*   enab   = (const int*)d_in[6];

    int B = in_sizes[0] / (N_TOK * CDIM);
    if (B < 1) B = 1;
    if (B > MAXB) B = MAXB;

    float* out = (float*)d_out;
    const size_t out_elems = (size_t)B * N_TOK * CDIM;
    const size_t sd_elems  = (size_t)HNUM * N_TOK * N_TOK;
    float* sd = nullptr;
    if ((size_t)out_size >= out_elems + sd_elems) {
        sd = out + out_elems;
        cudaMemsetAsync(sd, 0, sd_elems * sizeof(float));
    }

    const int dyn = (RPB * DH + RPB * N_TOK) * (int)sizeof(unsigned); // 34816 B
    cudaFuncSetAttribute(attn_topk_kernel,
                         cudaFuncAttributeMaxDynamicSharedMemorySize, dyn);

    dim3 qg(3 * CDIM / BMN, (B * N_TOK) / BMN);   // 36 x 64
    qkv_gemm_kernel<<<qg, 256>>>(x, qkv_w, B);

    attn_topk_kernel<<<B * HNUM * (N_TOK / RPB), 256, dyn>>>(B, cscore, cntr, enab, sd);

    dim3 pg(CDIM / BMN, (B * N_TOK) / BMN);       // 12 x 64
    proj_gemm_kernel<<<pg, 256>>>(proj_w, proj_b, out);
}